// round 8
// baseline (speedup 1.0000x reference)
#include <cuda_runtime.h>
#include <cuda_bf16.h>
#include <cstdint>

// ---------------- problem constants ----------------
#define NS    48
#define DIM   256
#define H     8
#define HD    32
#define NW    1728
#define NTOK  110592
#define QKVN  768
#define NKC   8             // K chunks (BK = 32)
#define STAGE_B 32768       // bytes per pipeline stage (4 planes x 8KB)

// ---------------- scratch ----------------
__device__ float g_qkv[(size_t)NTOK * QKVN];
__device__ __align__(16) __nv_bfloat16 g_xhi[(size_t)NTOK * DIM];
__device__ __align__(16) __nv_bfloat16 g_xlo[(size_t)NTOK * DIM];
__device__ __align__(16) __nv_bfloat16 g_ahi[(size_t)NTOK * DIM];
__device__ __align__(16) __nv_bfloat16 g_alo[(size_t)NTOK * DIM];
__device__ __align__(16) __nv_bfloat16 g_wqkv_hi[(size_t)QKVN * DIM];
__device__ __align__(16) __nv_bfloat16 g_wqkv_lo[(size_t)QKVN * DIM];
__device__ __align__(16) __nv_bfloat16 g_wout_hi[(size_t)DIM * DIM];
__device__ __align__(16) __nv_bfloat16 g_wout_lo[(size_t)DIM * DIM];

__device__ __forceinline__ int src_token(int t) {
    int win = t >> 6, i = t & 63;
    int a = win / 144, b = (win / 12) % 12, c = win % 12;
    int ix = i >> 4, iy = (i >> 2) & 3, iz = i & 3;
    int X = a * 4 + ix + 2; if (X >= NS) X -= NS;
    int Y = b * 4 + iy + 2; if (Y >= NS) Y -= NS;
    int Z = c * 4 + iz + 2; if (Z >= NS) Z -= NS;
    return (X * NS + Y) * NS + Z;
}

__device__ __forceinline__ void bf16_split(float x, __nv_bfloat16& hi, __nv_bfloat16& lo) {
    hi = __float2bfloat16_rn(x);
    lo = __float2bfloat16_rn(x - __bfloat162float(hi));
}

// ---------------- MMA / ldmatrix helpers ----------------
__device__ __forceinline__ void mma_bf16(float* d, const unsigned* a, const unsigned* b) {
    asm volatile(
        "mma.sync.aligned.m16n8k16.row.col.f32.bf16.bf16.f32 "
        "{%0,%1,%2,%3},{%4,%5,%6,%7},{%8,%9},{%0,%1,%2,%3};"
        : "+f"(d[0]), "+f"(d[1]), "+f"(d[2]), "+f"(d[3])
        : "r"(a[0]), "r"(a[1]), "r"(a[2]), "r"(a[3]), "r"(b[0]), "r"(b[1]));
}
__device__ __forceinline__ void ldsm_x4(uint32_t addr, unsigned r[4]) {
    asm volatile("ldmatrix.sync.aligned.m8n8.x4.shared.b16 {%0,%1,%2,%3}, [%4];"
                 : "=r"(r[0]), "=r"(r[1]), "=r"(r[2]), "=r"(r[3]) : "r"(addr));
}
#define CP_ASYNC16(dst, src) \
    asm volatile("cp.async.ca.shared.global [%0], [%1], 16;" :: "r"(dst), "l"(src) : "memory")
#define CP_COMMIT() asm volatile("cp.async.commit_group;" ::: "memory")
#define CP_WAIT1()  asm volatile("cp.async.wait_group 1;" ::: "memory")

// ---------------- prep: split x into bf16 hi/lo planes ----------------
__global__ __launch_bounds__(256) void split_x_kernel(const float4* __restrict__ x) {
    size_t i = (size_t)blockIdx.x * blockDim.x + threadIdx.x;
    float4 v = x[i];
    __nv_bfloat16 h0, l0, h1, l1;
    __nv_bfloat162 hp, lp;
    bf16_split(v.x, h0, l0); bf16_split(v.y, h1, l1);
    hp.x = h0; hp.y = h1; lp.x = l0; lp.y = l1;
    ((__nv_bfloat162*)g_xhi)[2 * i]     = hp;
    ((__nv_bfloat162*)g_xlo)[2 * i]     = lp;
    bf16_split(v.z, h0, l0); bf16_split(v.w, h1, l1);
    hp.x = h0; hp.y = h1; lp.x = l0; lp.y = l1;
    ((__nv_bfloat162*)g_xhi)[2 * i + 1] = hp;
    ((__nv_bfloat162*)g_xlo)[2 * i + 1] = lp;
}

// ---------------- prep: transpose + split weights ----------------
template<bool QKV>
__global__ void transpose_split(const float* __restrict__ W) {
    __shared__ float tile[32][33];
    const int N = QKV ? QKVN : DIM;
    __nv_bfloat16* Whi = QKV ? g_wqkv_hi : g_wout_hi;
    __nv_bfloat16* Wlo = QKV ? g_wqkv_lo : g_wout_lo;
    int bx = blockIdx.x * 32, by = blockIdx.y * 32;
    #pragma unroll
    for (int i = 0; i < 32; i += 8)
        tile[threadIdx.y + i][threadIdx.x] = W[(size_t)(by + threadIdx.y + i) * N + bx + threadIdx.x];
    __syncthreads();
    #pragma unroll
    for (int i = 0; i < 32; i += 8) {
        float v = tile[threadIdx.x][threadIdx.y + i];
        __nv_bfloat16 h, l;
        bf16_split(v, h, l);
        size_t o = (size_t)(bx + threadIdx.y + i) * DIM + by + threadIdx.x;
        Whi[o] = h; Wlo[o] = l;
    }
}

// ---------------- bf16x3 GEMM, BK=32, 3-stage cp.async --------------------------
// smem stage (32 KB): Ahi|Alo|Bhi|Blo, each plane = [4 k8grp][128 row][16 B].
template<int NBLK, bool GATHER_A, bool SCATTER_OUT>
__global__ __launch_bounds__(256, 2) void gemm_bf16x3(
        const float* __restrict__ bias, float* __restrict__ OutExt) {
    extern __shared__ char sm[];
    const uint32_t SBASE = (uint32_t)__cvta_generic_to_shared(sm);

    const int tid = threadIdx.x;
    const int warp = tid >> 5, lane = tid & 31;
    const int g = lane >> 2, l4 = lane & 3;
    const int wm = (warp >> 2) * 64, wn = (warp & 3) * 32;

    const __nv_bfloat16* Ahi = GATHER_A ? g_xhi : g_ahi;
    const __nv_bfloat16* Alo = GATHER_A ? g_xlo : g_alo;
    const __nv_bfloat16* Bhi = GATHER_A ? g_wqkv_hi : g_wout_hi;
    const __nv_bfloat16* Blo = GATHER_A ? g_wqkv_lo : g_wout_lo;
    float* Out = SCATTER_OUT ? OutExt : g_qkv;
    const int NOUT = NBLK * 128;

    const int mb = blockIdx.y * 128, nb = blockIdx.x * 128;

    // loader: 256 threads = 128 rows x 2 k16-halves of the 32-chunk
    const int lrow = tid & 127;
    const int half = tid >> 7;
    const int tokA = GATHER_A ? src_token(mb + lrow) : (mb + lrow);
    const __nv_bfloat16* aHiP = Ahi + (size_t)tokA * DIM + half * 16;
    const __nv_bfloat16* aLoP = Alo + (size_t)tokA * DIM + half * 16;
    const __nv_bfloat16* bHiP = Bhi + (size_t)(nb + lrow) * DIM + half * 16;
    const __nv_bfloat16* bLoP = Blo + (size_t)(nb + lrow) * DIM + half * 16;
    const uint32_t dstBase = SBASE + (2 * half) * 2048 + lrow * 16;   // k8 grp 2*half

    const int rowsel = (lane & 7) + ((lane >> 3) & 1) * 8;
    const uint32_t khoff = (uint32_t)(lane >> 4) * 2048;

    float acc[4][4][4] = {};

    #pragma unroll
    for (int p = 0; p < 2; p++) {
        const uint32_t d = dstBase + p * STAGE_B;
        CP_ASYNC16(d,                 aHiP + p * 32);
        CP_ASYNC16(d + 2048,          aHiP + p * 32 + 8);
        CP_ASYNC16(d + 8192,          aLoP + p * 32);
        CP_ASYNC16(d + 8192 + 2048,   aLoP + p * 32 + 8);
        CP_ASYNC16(d + 16384,         bHiP + p * 32);
        CP_ASYNC16(d + 16384 + 2048,  bHiP + p * 32 + 8);
        CP_ASYNC16(d + 24576,         bLoP + p * 32);
        CP_ASYNC16(d + 24576 + 2048,  bLoP + p * 32 + 8);
        CP_COMMIT();
    }

    #pragma unroll 1
    for (int kt = 0; kt < NKC; kt++) {
        CP_WAIT1();
        __syncthreads();
        if (kt + 2 < NKC) {
            const uint32_t d = dstBase + ((kt + 2) % 3) * STAGE_B;
            CP_ASYNC16(d,                 aHiP + (kt + 2) * 32);
            CP_ASYNC16(d + 2048,          aHiP + (kt + 2) * 32 + 8);
            CP_ASYNC16(d + 8192,          aLoP + (kt + 2) * 32);
            CP_ASYNC16(d + 8192 + 2048,   aLoP + (kt + 2) * 32 + 8);
            CP_ASYNC16(d + 16384,         bHiP + (kt + 2) * 32);
            CP_ASYNC16(d + 16384 + 2048,  bHiP + (kt + 2) * 32 + 8);
            CP_ASYNC16(d + 24576,         bLoP + (kt + 2) * 32);
            CP_ASYNC16(d + 24576 + 2048,  bLoP + (kt + 2) * 32 + 8);
        }
        CP_COMMIT();

        const uint32_t sst = SBASE + (kt % 3) * STAGE_B + khoff;
        #pragma unroll
        for (int kk = 0; kk < 2; kk++) {
            const uint32_t s = sst + kk * 4096;
            unsigned bhi[4][2], blo[4][2];
            #pragma unroll
            for (int j2 = 0; j2 < 2; j2++) {
                const uint32_t off = (uint32_t)(wn + j2 * 16 + rowsel) * 16;
                unsigned th[4], tl[4];
                ldsm_x4(s + 16384 + off, th);
                ldsm_x4(s + 24576 + off, tl);
                bhi[2 * j2][0] = th[0]; bhi[2 * j2][1] = th[2];
                bhi[2 * j2 + 1][0] = th[1]; bhi[2 * j2 + 1][1] = th[3];
                blo[2 * j2][0] = tl[0]; blo[2 * j2][1] = tl[2];
                blo[2 * j2 + 1][0] = tl[1]; blo[2 * j2 + 1][1] = tl[3];
            }
            #pragma unroll
            for (int i = 0; i < 4; i++) {
                const uint32_t off = (uint32_t)(wm + i * 16 + rowsel) * 16;
                unsigned ahi[4], alo[4];
                ldsm_x4(s + off, ahi);
                ldsm_x4(s + 8192 + off, alo);
                #pragma unroll
                for (int j = 0; j < 4; j++) {
                    mma_bf16(acc[i][j], ahi, bhi[j]);
                    mma_bf16(acc[i][j], alo, bhi[j]);
                    mma_bf16(acc[i][j], ahi, blo[j]);
                }
            }
        }
    }

    #pragma unroll
    for (int i = 0; i < 4; i++) {
        const int orow = mb + wm + i * 16 + g;
        const int r0 = SCATTER_OUT ? src_token(orow) : orow;
        const int r1 = SCATTER_OUT ? src_token(orow + 8) : (orow + 8);
        #pragma unroll
        for (int j = 0; j < 4; j++) {
            int c = nb + wn + j * 8 + 2 * l4;
            float bx = 0.f, by = 0.f;
            if (SCATTER_OUT) { bx = bias[c]; by = bias[c + 1]; }
            *(float2*)&Out[(size_t)r0 * NOUT + c] = make_float2(acc[i][j][0] + bx, acc[i][j][1] + by);
            *(float2*)&Out[(size_t)r1 * NOUT + c] = make_float2(acc[i][j][2] + bx, acc[i][j][3] + by);
        }
    }
}

// ---------------- bf16 tensor-core attention -----------------------------------
// smem planes (dynamic): QHI/QLO [64][40], KHI/KLO [64][40], VTHI/VTLO [32][88],
// PHI/PLO [4][16][88].  Row strides 80B / 176B are ldsm-phase conflict-free.
#define QROW 40
#define VROW 88
#define OFF_QHI 0
#define OFF_QLO 5120
#define OFF_KHI 10240
#define OFF_KLO 15360
#define OFF_VTHI 20480
#define OFF_VTLO 26112
#define OFF_PHI 31744
#define OFF_PLO 43008
#define ATTN_SMEM 54272

__global__ __launch_bounds__(128) void attn_tc() {
    extern __shared__ char sm[];
    __nv_bfloat16* sb = (__nv_bfloat16*)sm;
    const uint32_t SB = (uint32_t)__cvta_generic_to_shared(sm);

    const int wp = blockIdx.x, h = blockIdx.y;
    const int ap = wp / 144, bp = (wp / 12) % 12, cp = wp % 12;
    const int wqk = bp * 144 + cp * 12 + ap;
    const int tid = threadIdx.x;
    const int warp = tid >> 5, lane = tid & 31;
    const int g = lane >> 2, l4 = lane & 3;
    const int rowsel = (lane & 7) + ((lane >> 3) & 1) * 8;
    const uint32_t coff = (uint32_t)(lane >> 4) * 16;

    // ---- load + split Q,K (window wqk) and V^T (window wp) ----
    {
        const int r = tid >> 1, half = (tid & 1) * 16;
        const float* qg = g_qkv + (size_t)(wqk * 64 + r) * QKVN + h * HD + half;
        const float* vg = g_qkv + (size_t)(wp * 64 + r) * QKVN + 512 + h * HD + half;
        #pragma unroll
        for (int c = 0; c < 4; c++) {
            float4 qv = *(const float4*)(qg + 4 * c);
            float4 kv = *(const float4*)(qg + 256 + 4 * c);
            float4 vv = *(const float4*)(vg + 4 * c);
            const float qa[4] = {qv.x, qv.y, qv.z, qv.w};
            const float ka[4] = {kv.x, kv.y, kv.z, kv.w};
            const float va[4] = {vv.x, vv.y, vv.z, vv.w};
            #pragma unroll
            for (int e = 0; e < 4; e++) {
                const int d = half + 4 * c + e;
                __nv_bfloat16 hh, ll;
                bf16_split(qa[e], hh, ll);
                sb[(OFF_QHI >> 1) + r * QROW + d] = hh;
                sb[(OFF_QLO >> 1) + r * QROW + d] = ll;
                bf16_split(ka[e], hh, ll);
                sb[(OFF_KHI >> 1) + r * QROW + d] = hh;
                sb[(OFF_KLO >> 1) + r * QROW + d] = ll;
                bf16_split(va[e], hh, ll);
                sb[(OFF_VTHI >> 1) + d * VROW + r] = hh;
                sb[(OFF_VTLO >> 1) + d * VROW + r] = ll;
            }
        }
    }
    __syncthreads();

    const int m0 = warp * 16;
    const int maskbits = ((bp == 11) << 5) | ((cp == 11) << 3) | ((ap == 11) << 1);
    const float scale = 0.1767766952966369f;

    // ---- S = Q K^T (strip 16x64), bf16x3, k16 steps ----
    float s[8][4] = {};
    #pragma unroll
    for (int kt = 0; kt < 2; kt++) {
        const uint32_t kb = kt * 32 + coff;
        unsigned ahi[4], alo[4];
        ldsm_x4(SB + OFF_QHI + (m0 + rowsel) * 80 + kb, ahi);
        ldsm_x4(SB + OFF_QLO + (m0 + rowsel) * 80 + kb, alo);
        #pragma unroll
        for (int j2 = 0; j2 < 4; j2++) {
            unsigned th[4], tl[4];
            ldsm_x4(SB + OFF_KHI + (j2 * 16 + rowsel) * 80 + kb, th);
            ldsm_x4(SB + OFF_KLO + (j2 * 16 + rowsel) * 80 + kb, tl);
            unsigned bh0[2] = {th[0], th[2]}, bh1[2] = {th[1], th[3]};
            unsigned bl0[2] = {tl[0], tl[2]}, bl1[2] = {tl[1], tl[3]};
            mma_bf16(s[2 * j2],     ahi, bh0);
            mma_bf16(s[2 * j2],     alo, bh0);
            mma_bf16(s[2 * j2],     ahi, bl0);
            mma_bf16(s[2 * j2 + 1], ahi, bh1);
            mma_bf16(s[2 * j2 + 1], alo, bh1);
            mma_bf16(s[2 * j2 + 1], ahi, bl1);
        }
    }

    // ---- mask + softmax ----
    const int i0 = m0 + g, i1 = m0 + g + 8;
    float mx0 = -1e30f, mx1 = -1e30f;
    #pragma unroll
    for (int nt = 0; nt < 8; nt++) {
        const int j0 = nt * 8 + 2 * l4;
        s[nt][0] = ((i0 ^ j0) & maskbits) ? -1e30f : s[nt][0] * scale;
        s[nt][1] = ((i0 ^ (j0 + 1)) & maskbits) ? -1e30f : s[nt][1] * scale;
        s[nt][2] = ((i1 ^ j0) & maskbits) ? -1e30f : s[nt][2] * scale;
        s[nt][3] = ((i1 ^ (j0 + 1)) & maskbits) ? -1e30f : s[nt][3] * scale;
        mx0 = fmaxf(mx0, fmaxf(s[nt][0], s[nt][1]));
        mx1 = fmaxf(mx1, fmaxf(s[nt][2], s[nt][3]));
    }
    mx0 = fmaxf(mx0, __shfl_xor_sync(0xFFFFFFFF, mx0, 1));
    mx0 = fmaxf(mx0, __shfl_xor_sync(0xFFFFFFFF, mx0, 2));
    mx1 = fmaxf(mx1, __shfl_xor_sync(0xFFFFFFFF, mx1, 1));
    mx1 = fmaxf(mx1, __shfl_xor_sync(0xFFFFFFFF, mx1, 2));
    float sm0 = 0.f, sm1 = 0.f;
    #pragma unroll
    for (int nt = 0; nt < 8; nt++) {
        s[nt][0] = __expf(s[nt][0] - mx0);
        s[nt][1] = __expf(s[nt][1] - mx0);
        s[nt][2] = __expf(s[nt][2] - mx1);
        s[nt][3] = __expf(s[nt][3] - mx1);
        sm0 += s[nt][0] + s[nt][1];
        sm1 += s[nt][2] + s[nt][3];
    }
    sm0 += __shfl_xor_sync(0xFFFFFFFF, sm0, 1);
    sm0 += __shfl_xor_sync(0xFFFFFFFF, sm0, 2);
    sm1 += __shfl_xor_sync(0xFFFFFFFF, sm1, 1);
    sm1 += __shfl_xor_sync(0xFFFFFFFF, sm1, 2);
    const float inv0 = 1.f / sm0, inv1 = 1.f / sm1;

    // ---- split-stage P in per-warp bf16 planes ----
    {
        __nv_bfloat16* phi = sb + (OFF_PHI >> 1) + warp * 16 * VROW;
        __nv_bfloat16* plo = sb + (OFF_PLO >> 1) + warp * 16 * VROW;
        #pragma unroll
        for (int nt = 0; nt < 8; nt++) {
            const int j0 = nt * 8 + 2 * l4;
            __nv_bfloat16 hh, ll;
            bf16_split(s[nt][0], hh, ll); phi[g * VROW + j0] = hh;       plo[g * VROW + j0] = ll;
            bf16_split(s[nt][1], hh, ll); phi[g * VROW + j0 + 1] = hh;   plo[g * VROW + j0 + 1] = ll;
            bf16_split(s[nt][2], hh, ll); phi[(g + 8) * VROW + j0] = hh; plo[(g + 8) * VROW + j0] = ll;
            bf16_split(s[nt][3], hh, ll); phi[(g + 8) * VROW + j0 + 1] = hh; plo[(g + 8) * VROW + j0 + 1] = ll;
        }
    }
    __syncwarp();

    // ---- O = P V (strip 16x32), bf16x3 ----
    float o[4][4] = {};
    const uint32_t PHIb = SB + OFF_PHI + warp * 16 * VROW * 2;
    const uint32_t PLOb = SB + OFF_PLO + warp * 16 * VROW * 2;
    #pragma unroll
    for (int kt = 0; kt < 4; kt++) {
        const uint32_t kb = kt * 32 + coff;
        unsigned ahi[4], alo[4];
        ldsm_x4(PHIb + rowsel * (VROW * 2) + kb, ahi);
        ldsm_x4(PLOb + rowsel * (VROW * 2) + kb, alo);
        #pragma unroll
        for (int d2 = 0; d2 < 2; d2++) {
            unsigned th[4], tl[4];
            ldsm_x4(SB + OFF_VTHI + (d2 * 16 + rowsel) * (VROW * 2) + kb, th);
            ldsm_x4(SB + OFF_VTLO + (d2 * 16 + rowsel) * (VROW * 2) + kb, tl);
            unsigned bh0[2] = {th[0], th[2]}, bh1[2] = {th[1], th[3]};
            unsigned bl0[2] = {tl[0], tl[2]}, bl1[2] = {tl[1], tl[3]};
            mma_bf16(o[2 * d2],     ahi, bh0);
            mma_bf16(o[2 * d2],     alo, bh0);
            mma_bf16(o[2 * d2],     ahi, bl0);
            mma_bf16(o[2 * d2 + 1], ahi, bh1);
            mma_bf16(o[2 * d2 + 1], alo, bh1);
            mma_bf16(o[2 * d2 + 1], ahi, bl1);
        }
    }

    // ---- normalize + split-store to g_ahi/g_alo ----
    const size_t off0 = (size_t)(wp * 64 + i0) * DIM + h * HD;
    const size_t off1 = (size_t)(wp * 64 + i1) * DIM + h * HD;
    #pragma unroll
    for (int dt = 0; dt < 4; dt++) {
        const int d0 = dt * 8 + 2 * l4;
        float v0 = o[dt][0] * inv0, v1 = o[dt][1] * inv0;
        float v2 = o[dt][2] * inv1, v3 = o[dt][3] * inv1;
        __nv_bfloat16 h0, l0, h1, l1;
        __nv_bfloat162 hp, lp;
        bf16_split(v0, h0, l0); bf16_split(v1, h1, l1);
        hp.x = h0; hp.y = h1; lp.x = l0; lp.y = l1;
        *(__nv_bfloat162*)&g_ahi[off0 + d0] = hp;
        *(__nv_bfloat162*)&g_alo[off0 + d0] = lp;
        bf16_split(v2, h0, l0); bf16_split(v3, h1, l1);
        hp.x = h0; hp.y = h1; lp.x = l0; lp.y = l1;
        *(__nv_bfloat162*)&g_ahi[off1 + d0] = hp;
        *(__nv_bfloat162*)&g_alo[off1 + d0] = lp;
    }
}

// ---------------- launch ----------------
extern "C" void kernel_launch(void* const* d_in, const int* in_sizes, int n_in,
                              void* d_out, int out_size) {
    const float* x     = (const float*)d_in[0];
    const float* w_qkv = (const float*)d_in[1];
    const float* w_out = (const float*)d_in[2];
    const float* b_out = (const float*)d_in[3];
    float* out = (float*)d_out;

    const int smem_sz = 3 * STAGE_B;   // 98304
    cudaFuncSetAttribute(gemm_bf16x3<6, true, false>,
                         cudaFuncAttributeMaxDynamicSharedMemorySize, smem_sz);
    cudaFuncSetAttribute(gemm_bf16x3<2, false, true>,
                         cudaFuncAttributeMaxDynamicSharedMemorySize, smem_sz);
    cudaFuncSetAttribute(attn_tc,
                         cudaFuncAttributeMaxDynamicSharedMemorySize, ATTN_SMEM);

    split_x_kernel<<<NTOK * 64 / 256, 256>>>((const float4*)x);
    transpose_split<true> <<<dim3(QKVN / 32, DIM / 32), dim3(32, 8)>>>(w_qkv);
    transpose_split<false><<<dim3(DIM / 32,  DIM / 32), dim3(32, 8)>>>(w_out);
    gemm_bf16x3<6, true, false><<<dim3(6, NTOK / 128), 256, smem_sz>>>(nullptr, nullptr);
    attn_tc<<<dim3(NW, H), 128, ATTN_SMEM>>>();
    gemm_bf16x3<2, false, true><<<dim3(2, NTOK / 128), 256, smem_sz>>>(b_out, out);
}

// round 9
// speedup vs baseline: 1.1188x; 1.1188x over previous
#include <cuda_runtime.h>
#include <cuda_bf16.h>
#include <cstdint>

// ---------------- problem constants ----------------
#define NS    48
#define DIM   256
#define H     8
#define HD    32
#define NW    1728
#define NTOK  110592
#define QKVN  768

// A-resident GEMM geometry
#define A_BYTES   131072      // 2 planes x 16 chunks x 4KB
#define B_STAGE   8192        // Bhi|Blo per chunk
#define GEMM_SMEM (A_BYTES + 3 * B_STAGE)   // 155648

// ---------------- scratch ----------------
__device__ float g_qkv[(size_t)NTOK * QKVN];
__device__ float g_attn[(size_t)NTOK * DIM];
__device__ __align__(16) __nv_bfloat16 g_xhi[(size_t)NTOK * DIM];
__device__ __align__(16) __nv_bfloat16 g_xlo[(size_t)NTOK * DIM];
__device__ __align__(16) __nv_bfloat16 g_ahi[(size_t)NTOK * DIM];
__device__ __align__(16) __nv_bfloat16 g_alo[(size_t)NTOK * DIM];
__device__ __align__(16) __nv_bfloat16 g_wqkv_hi[(size_t)QKVN * DIM];
__device__ __align__(16) __nv_bfloat16 g_wqkv_lo[(size_t)QKVN * DIM];
__device__ __align__(16) __nv_bfloat16 g_wout_hi[(size_t)DIM * DIM];
__device__ __align__(16) __nv_bfloat16 g_wout_lo[(size_t)DIM * DIM];

__device__ __forceinline__ int src_token(int t) {
    int win = t >> 6, i = t & 63;
    int a = win / 144, b = (win / 12) % 12, c = win % 12;
    int ix = i >> 4, iy = (i >> 2) & 3, iz = i & 3;
    int X = a * 4 + ix + 2; if (X >= NS) X -= NS;
    int Y = b * 4 + iy + 2; if (Y >= NS) Y -= NS;
    int Z = c * 4 + iz + 2; if (Z >= NS) Z -= NS;
    return (X * NS + Y) * NS + Z;
}

__device__ __forceinline__ void bf16_split(float x, __nv_bfloat16& hi, __nv_bfloat16& lo) {
    hi = __float2bfloat16_rn(x);
    lo = __float2bfloat16_rn(x - __bfloat162float(hi));
}

// ---------------- MMA / ldmatrix / cp.async helpers ----------------
__device__ __forceinline__ void mma_bf16(float* d, const unsigned* a, const unsigned* b) {
    asm volatile(
        "mma.sync.aligned.m16n8k16.row.col.f32.bf16.bf16.f32 "
        "{%0,%1,%2,%3},{%4,%5,%6,%7},{%8,%9},{%0,%1,%2,%3};"
        : "+f"(d[0]), "+f"(d[1]), "+f"(d[2]), "+f"(d[3])
        : "r"(a[0]), "r"(a[1]), "r"(a[2]), "r"(a[3]), "r"(b[0]), "r"(b[1]));
}
__device__ __forceinline__ void ldsm_x4(uint32_t addr, unsigned r[4]) {
    asm volatile("ldmatrix.sync.aligned.m8n8.x4.shared.b16 {%0,%1,%2,%3}, [%4];"
                 : "=r"(r[0]), "=r"(r[1]), "=r"(r[2]), "=r"(r[3]) : "r"(addr));
}
#define CP_ASYNC16(dst, src) \
    asm volatile("cp.async.ca.shared.global [%0], [%1], 16;" :: "r"(dst), "l"(src) : "memory")
#define CP_COMMIT() asm volatile("cp.async.commit_group;" ::: "memory")
#define CP_WAIT1()  asm volatile("cp.async.wait_group 1;" ::: "memory")

// tf32 helpers (attention)
__device__ __forceinline__ void tf32_split(float x, unsigned& hi, unsigned& lo) {
    unsigned h;
    asm("cvt.rna.tf32.f32 %0, %1;" : "=r"(h) : "f"(x));
    float l = x - __uint_as_float(h);
    unsigned lw;
    asm("cvt.rna.tf32.f32 %0, %1;" : "=r"(lw) : "f"(l));
    hi = h; lo = lw;
}
__device__ __forceinline__ void mma_tf32(float* d, const unsigned* a, const unsigned* b) {
    asm volatile(
        "mma.sync.aligned.m16n8k8.row.col.f32.tf32.tf32.f32 "
        "{%0,%1,%2,%3},{%4,%5,%6,%7},{%8,%9},{%0,%1,%2,%3};"
        : "+f"(d[0]), "+f"(d[1]), "+f"(d[2]), "+f"(d[3])
        : "r"(a[0]), "r"(a[1]), "r"(a[2]), "r"(a[3]), "r"(b[0]), "r"(b[1]));
}

// ---------------- prep kernels ----------------
__global__ __launch_bounds__(256) void split_x_kernel(const float4* __restrict__ x) {
    size_t i = (size_t)blockIdx.x * blockDim.x + threadIdx.x;
    float4 v = x[i];
    __nv_bfloat16 h0, l0, h1, l1;
    __nv_bfloat162 hp, lp;
    bf16_split(v.x, h0, l0); bf16_split(v.y, h1, l1);
    hp.x = h0; hp.y = h1; lp.x = l0; lp.y = l1;
    ((__nv_bfloat162*)g_xhi)[2 * i]     = hp;
    ((__nv_bfloat162*)g_xlo)[2 * i]     = lp;
    bf16_split(v.z, h0, l0); bf16_split(v.w, h1, l1);
    hp.x = h0; hp.y = h1; lp.x = l0; lp.y = l1;
    ((__nv_bfloat162*)g_xhi)[2 * i + 1] = hp;
    ((__nv_bfloat162*)g_xlo)[2 * i + 1] = lp;
}

template<bool QKV>
__global__ void transpose_split(const float* __restrict__ W) {
    __shared__ float tile[32][33];
    const int N = QKV ? QKVN : DIM;
    __nv_bfloat16* Whi = QKV ? g_wqkv_hi : g_wout_hi;
    __nv_bfloat16* Wlo = QKV ? g_wqkv_lo : g_wout_lo;
    int bx = blockIdx.x * 32, by = blockIdx.y * 32;
    #pragma unroll
    for (int i = 0; i < 32; i += 8)
        tile[threadIdx.y + i][threadIdx.x] = W[(size_t)(by + threadIdx.y + i) * N + bx + threadIdx.x];
    __syncthreads();
    #pragma unroll
    for (int i = 0; i < 32; i += 8) {
        float v = tile[threadIdx.x][threadIdx.y + i];
        __nv_bfloat16 h, l;
        bf16_split(v, h, l);
        size_t o = (size_t)(bx + threadIdx.y + i) * DIM + by + threadIdx.x;
        Whi[o] = h; Wlo[o] = l;
    }
}

// ---------------- A-resident bf16x3 GEMM --------------------------------------
// Block = one 128-row m-tile. A planes (hi|lo, [16 chunk][2 k8][128 row][16B])
// loaded to smem once; loop over NBLK n-tiles streaming B through a 3-stage ring.
template<int NBLK, bool GATHER_A, bool SCATTER_OUT>
__global__ __launch_bounds__(256, 1) void gemm_ares(
        const float* __restrict__ bias, float* __restrict__ OutExt) {
    extern __shared__ char smc[];
    const uint32_t ABASE = (uint32_t)__cvta_generic_to_shared(smc);
    const uint32_t BBASE = ABASE + A_BYTES;

    const int tid = threadIdx.x;
    const int warp = tid >> 5, lane = tid & 31;
    const int g = lane >> 2, l4 = lane & 3;
    const int wm = (warp >> 2) * 64, wn = (warp & 3) * 32;

    const __nv_bfloat16* Ahi = GATHER_A ? g_xhi : g_ahi;
    const __nv_bfloat16* Alo = GATHER_A ? g_xlo : g_alo;
    const __nv_bfloat16* Bhi = GATHER_A ? g_wqkv_hi : g_wout_hi;
    const __nv_bfloat16* Blo = GATHER_A ? g_wqkv_lo : g_wout_lo;
    float* Out = SCATTER_OUT ? OutExt : g_qkv;
    const int NOUT = NBLK * 128;

    const int mb = blockIdx.x * 128;
    const int lrow = tid & 127;
    const int half = tid >> 7;

    // ---- load A planes once (32 cp.async x 16B per thread) ----
    {
        const int tok = GATHER_A ? src_token(mb + lrow) : (mb + lrow);
        const __nv_bfloat16* ah = Ahi + (size_t)tok * DIM + half * 8;
        const __nv_bfloat16* al = Alo + (size_t)tok * DIM + half * 8;
        const uint32_t d0 = ABASE + half * 2048 + lrow * 16;
        #pragma unroll
        for (int kt = 0; kt < 16; kt++) {
            CP_ASYNC16(d0 + kt * 4096,         ah + kt * 16);
            CP_ASYNC16(d0 + kt * 4096 + 65536, al + kt * 16);
        }
        CP_COMMIT();
    }

    // B loader base (row index within current n-tile)
    const __nv_bfloat16* bHiRow = Bhi + (size_t)lrow * DIM + half * 8;
    const __nv_bfloat16* bLoRow = Blo + (size_t)lrow * DIM + half * 8;
    const uint32_t bDst = BBASE + half * 2048 + lrow * 16;

    // prologue: B chunks 0,1 (flat chunk id: c -> nt=c/16, kt=c%16)
    #pragma unroll
    for (int p = 0; p < 2; p++) {
        CP_ASYNC16(bDst + p * B_STAGE,        bHiRow + p * 16);
        CP_ASYNC16(bDst + p * B_STAGE + 4096, bLoRow + p * 16);
        CP_COMMIT();
    }

    const int rowsel = (lane & 7) + ((lane >> 3) & 1) * 8;
    const uint32_t khoff = (uint32_t)(lane >> 4) * 2048;

    float acc[4][4][4] = {};
    const int NCH = NBLK * 16;

    #pragma unroll 1
    for (int c = 0; c < NCH; c++) {
        CP_WAIT1();
        __syncthreads();
        if (c + 2 < NCH) {
            const int c2 = c + 2;
            const size_t boff = (size_t)((c2 >> 4) * 128) * DIM + (c2 & 15) * 16;
            const uint32_t d = bDst + (c2 % 3) * B_STAGE;
            CP_ASYNC16(d,        bHiRow + boff);
            CP_ASYNC16(d + 4096, bLoRow + boff);
        }
        CP_COMMIT();

        const int kt = c & 15;
        const uint32_t sA = ABASE + kt * 4096 + khoff;
        const uint32_t sB = BBASE + (c % 3) * B_STAGE + khoff;

        unsigned bhi[4][2], blo[4][2];
        #pragma unroll
        for (int j2 = 0; j2 < 2; j2++) {
            const uint32_t off = (uint32_t)(wn + j2 * 16 + rowsel) * 16;
            unsigned th[4], tl[4];
            ldsm_x4(sB + off, th);
            ldsm_x4(sB + 4096 + off, tl);
            bhi[2 * j2][0] = th[0]; bhi[2 * j2][1] = th[2];
            bhi[2 * j2 + 1][0] = th[1]; bhi[2 * j2 + 1][1] = th[3];
            blo[2 * j2][0] = tl[0]; blo[2 * j2][1] = tl[2];
            blo[2 * j2 + 1][0] = tl[1]; blo[2 * j2 + 1][1] = tl[3];
        }
        #pragma unroll
        for (int i = 0; i < 4; i++) {
            const uint32_t off = (uint32_t)(wm + i * 16 + rowsel) * 16;
            unsigned ahi[4], alo[4];
            ldsm_x4(sA + off, ahi);
            ldsm_x4(sA + 65536 + off, alo);
            #pragma unroll
            for (int j = 0; j < 4; j++) {
                mma_bf16(acc[i][j], ahi, bhi[j]);
                mma_bf16(acc[i][j], alo, bhi[j]);
                mma_bf16(acc[i][j], ahi, blo[j]);
            }
        }

        if (kt == 15) {
            // epilogue for n-tile nt = c>>4 (register->gmem only; no smem, no sync)
            const int nb = (c >> 4) * 128;
            #pragma unroll
            for (int i = 0; i < 4; i++) {
                const int orow = mb + wm + i * 16 + g;
                const int r0 = SCATTER_OUT ? src_token(orow) : orow;
                const int r1 = SCATTER_OUT ? src_token(orow + 8) : (orow + 8);
                #pragma unroll
                for (int j = 0; j < 4; j++) {
                    int cc = nb + wn + j * 8 + 2 * l4;
                    float bx = 0.f, by = 0.f;
                    if (SCATTER_OUT) { bx = bias[cc]; by = bias[cc + 1]; }
                    *(float2*)&Out[(size_t)r0 * NOUT + cc] =
                        make_float2(acc[i][j][0] + bx, acc[i][j][1] + by);
                    *(float2*)&Out[(size_t)r1 * NOUT + cc] =
                        make_float2(acc[i][j][2] + bx, acc[i][j][3] + by);
                    acc[i][j][0] = acc[i][j][1] = acc[i][j][2] = acc[i][j][3] = 0.f;
                }
            }
        }
    }
}

// ---------------- tensor-core attention (R7 version; writes split planes) -----
__global__ __launch_bounds__(128) void attn_tc() {
    __shared__ float qs[64][36];
    __shared__ float ks[64][36];
    __shared__ float vst[32][68];
    __shared__ float ps[4][16][68];

    const int wp = blockIdx.x, h = blockIdx.y;
    const int ap = wp / 144, bp = (wp / 12) % 12, cp = wp % 12;
    const int wqk = bp * 144 + cp * 12 + ap;
    const int tid = threadIdx.x;
    const int warp = tid >> 5, lane = tid & 31;
    const int g = lane >> 2, l4 = lane & 3;

    {
        const int r = tid >> 1, half = (tid & 1) * 16;
        const float* qg = g_qkv + (size_t)(wqk * 64 + r) * QKVN + h * HD + half;
        const float* vg = g_qkv + (size_t)(wp * 64 + r) * QKVN + 512 + h * HD + half;
        #pragma unroll
        for (int c = 0; c < 4; c++) {
            float4 qv = *(const float4*)(qg + 4 * c);
            *(float4*)&qs[r][half + 4 * c] = qv;
            float4 kv = *(const float4*)(qg + 256 + 4 * c);
            *(float4*)&ks[r][half + 4 * c] = kv;
            float4 vv = *(const float4*)(vg + 4 * c);
            vst[half + 4 * c + 0][r] = vv.x;
            vst[half + 4 * c + 1][r] = vv.y;
            vst[half + 4 * c + 2][r] = vv.z;
            vst[half + 4 * c + 3][r] = vv.w;
        }
    }
    __syncthreads();

    const int m0 = warp * 16;
    const int maskbits = ((bp == 11) << 5) | ((cp == 11) << 3) | ((ap == 11) << 1);
    const float scale = 0.1767766952966369f;

    float s[8][4] = {};
    #pragma unroll
    for (int kt = 0; kt < 4; kt++) {
        const int k0 = kt * 8;
        unsigned ahi[4], alo[4];
        tf32_split(qs[m0 + g][k0 + l4],         ahi[0], alo[0]);
        tf32_split(qs[m0 + g + 8][k0 + l4],     ahi[1], alo[1]);
        tf32_split(qs[m0 + g][k0 + l4 + 4],     ahi[2], alo[2]);
        tf32_split(qs[m0 + g + 8][k0 + l4 + 4], ahi[3], alo[3]);
        #pragma unroll
        for (int nt = 0; nt < 8; nt++) {
            unsigned bhi[2], blo[2];
            tf32_split(ks[nt * 8 + g][k0 + l4],     bhi[0], blo[0]);
            tf32_split(ks[nt * 8 + g][k0 + l4 + 4], bhi[1], blo[1]);
            mma_tf32(s[nt], ahi, bhi);
            mma_tf32(s[nt], alo, bhi);
            mma_tf32(s[nt], ahi, blo);
        }
    }

    const int i0 = m0 + g, i1 = m0 + g + 8;
    float mx0 = -1e30f, mx1 = -1e30f;
    #pragma unroll
    for (int nt = 0; nt < 8; nt++) {
        const int j0 = nt * 8 + 2 * l4;
        s[nt][0] = ((i0 ^ j0) & maskbits) ? -1e30f : s[nt][0] * scale;
        s[nt][1] = ((i0 ^ (j0 + 1)) & maskbits) ? -1e30f : s[nt][1] * scale;
        s[nt][2] = ((i1 ^ j0) & maskbits) ? -1e30f : s[nt][2] * scale;
        s[nt][3] = ((i1 ^ (j0 + 1)) & maskbits) ? -1e30f : s[nt][3] * scale;
        mx0 = fmaxf(mx0, fmaxf(s[nt][0], s[nt][1]));
        mx1 = fmaxf(mx1, fmaxf(s[nt][2], s[nt][3]));
    }
    mx0 = fmaxf(mx0, __shfl_xor_sync(0xFFFFFFFF, mx0, 1));
    mx0 = fmaxf(mx0, __shfl_xor_sync(0xFFFFFFFF, mx0, 2));
    mx1 = fmaxf(mx1, __shfl_xor_sync(0xFFFFFFFF, mx1, 1));
    mx1 = fmaxf(mx1, __shfl_xor_sync(0xFFFFFFFF, mx1, 2));
    float sm0 = 0.f, sm1 = 0.f;
    #pragma unroll
    for (int nt = 0; nt < 8; nt++) {
        s[nt][0] = __expf(s[nt][0] - mx0);
        s[nt][1] = __expf(s[nt][1] - mx0);
        s[nt][2] = __expf(s[nt][2] - mx1);
        s[nt][3] = __expf(s[nt][3] - mx1);
        sm0 += s[nt][0] + s[nt][1];
        sm1 += s[nt][2] + s[nt][3];
    }
    sm0 += __shfl_xor_sync(0xFFFFFFFF, sm0, 1);
    sm0 += __shfl_xor_sync(0xFFFFFFFF, sm0, 2);
    sm1 += __shfl_xor_sync(0xFFFFFFFF, sm1, 1);
    sm1 += __shfl_xor_sync(0xFFFFFFFF, sm1, 2);
    const float inv0 = 1.f / sm0, inv1 = 1.f / sm1;

    #pragma unroll
    for (int nt = 0; nt < 8; nt++) {
        const int j0 = nt * 8 + 2 * l4;
        ps[warp][g][j0]         = s[nt][0];
        ps[warp][g][j0 + 1]     = s[nt][1];
        ps[warp][g + 8][j0]     = s[nt][2];
        ps[warp][g + 8][j0 + 1] = s[nt][3];
    }
    __syncwarp();

    float o[4][4] = {};
    #pragma unroll
    for (int kt = 0; kt < 8; kt++) {
        const int j0 = kt * 8;
        unsigned ahi[4], alo[4];
        tf32_split(ps[warp][g][j0 + l4],         ahi[0], alo[0]);
        tf32_split(ps[warp][g + 8][j0 + l4],     ahi[1], alo[1]);
        tf32_split(ps[warp][g][j0 + l4 + 4],     ahi[2], alo[2]);
        tf32_split(ps[warp][g + 8][j0 + l4 + 4], ahi[3], alo[3]);
        #pragma unroll
        for (int dt = 0; dt < 4; dt++) {
            unsigned bhi[2], blo[2];
            tf32_split(vst[dt * 8 + g][j0 + l4],     bhi[0], blo[0]);
            tf32_split(vst[dt * 8 + g][j0 + l4 + 4], bhi[1], blo[1]);
            mma_tf32(o[dt], ahi, bhi);
            mma_tf32(o[dt], alo, bhi);
            mma_tf32(o[dt], ahi, blo);
        }
    }

    const size_t off0 = (size_t)(wp * 64 + i0) * DIM + h * HD;
    const size_t off1 = (size_t)(wp * 64 + i1) * DIM + h * HD;
    #pragma unroll
    for (int dt = 0; dt < 4; dt++) {
        const int d0 = dt * 8 + 2 * l4;
        float v0 = o[dt][0] * inv0, v1 = o[dt][1] * inv0;
        float v2 = o[dt][2] * inv1, v3 = o[dt][3] * inv1;
        __nv_bfloat16 h0, l0, h1, l1;
        __nv_bfloat162 hp, lp;
        bf16_split(v0, h0, l0); bf16_split(v1, h1, l1);
        hp.x = h0; hp.y = h1; lp.x = l0; lp.y = l1;
        *(__nv_bfloat162*)&g_ahi[off0 + d0] = hp;
        *(__nv_bfloat162*)&g_alo[off0 + d0] = lp;
        bf16_split(v2, h0, l0); bf16_split(v3, h1, l1);
        hp.x = h0; hp.y = h1; lp.x = l0; lp.y = l1;
        *(__nv_bfloat162*)&g_ahi[off1 + d0] = hp;
        *(__nv_bfloat162*)&g_alo[off1 + d0] = lp;
    }
}

// ---------------- launch ----------------
extern "C" void kernel_launch(void* const* d_in, const int* in_sizes, int n_in,
                              void* d_out, int out_size) {
    const float* x     = (const float*)d_in[0];
    const float* w_qkv = (const float*)d_in[1];
    const float* w_out = (const float*)d_in[2];
    const float* b_out = (const float*)d_in[3];
    float* out = (float*)d_out;

    cudaFuncSetAttribute(gemm_ares<6, true, false>,
                         cudaFuncAttributeMaxDynamicSharedMemorySize, GEMM_SMEM);
    cudaFuncSetAttribute(gemm_ares<2, false, true>,
                         cudaFuncAttributeMaxDynamicSharedMemorySize, GEMM_SMEM);

    split_x_kernel<<<NTOK * 64 / 256, 256>>>((const float4*)x);
    transpose_split<true> <<<dim3(QKVN / 32, DIM / 32), dim3(32, 8)>>>(w_qkv);
    transpose_split<false><<<dim3(DIM / 32,  DIM / 32), dim3(32, 8)>>>(w_out);
    gemm_ares<6, true, false><<<NTOK / 128, 256, GEMM_SMEM>>>(nullptr, nullptr);
    attn_tc<<<dim3(NW, H), 128>>>();
    gemm_ares<2, false, true><<<NTOK / 128, 256, GEMM_SMEM>>>(b_out, out);
}